// round 7
// baseline (speedup 1.0000x reference)
#include <cuda_runtime.h>
#include <cstddef>

// Problem constants (fixed shapes from reference setup_inputs)
#define T_STEPS 16
#define B_SZ    512
#define F_IN    2048
#define H_SZ    2048
#define OUT_SZ  1024
#define BT      (B_SZ * T_STEPS)   // 8192

// Scratch (device globals: allocation-free per harness rules)
__device__ float g_H [ (size_t)BT  * H_SZ   ];  // 64 MB: all-timestep fc1 pre-activations
__device__ float g_s1[ (size_t)B_SZ * H_SZ  ];  // spikes of lif1 at current t (fp32 for GEMM2)
__device__ float g_v1[ (size_t)B_SZ * H_SZ  ];  // membrane lif1
__device__ float g_v2[ (size_t)B_SZ * OUT_SZ];  // membrane lif_out

// ---------------------------------------------------------------------------
// init: zero membranes (must happen every launch; deterministic)
// ---------------------------------------------------------------------------
__global__ void init_state_kernel() {
    size_t i = (size_t)blockIdx.x * blockDim.x + threadIdx.x;
    size_t n1 = (size_t)B_SZ * H_SZ;
    size_t n2 = (size_t)B_SZ * OUT_SZ;
    if (i < n1) g_v1[i] = 0.0f;
    if (i < n2) g_v2[i] = 0.0f;
}

// ---------------------------------------------------------------------------
// GEMM1 (FROZEN — bitwise contract with reference established in R6):
// C[M,N] = A[M,K] * B[N,K]^T, kc-blocked accumulation: NSPLIT contiguous
// chunks, each a serial ascending FMA chain from zero, sequential merge.
// ---------------------------------------------------------------------------
template<int BM, int BN, int BK, int TM, int TN, int NSPLIT>
__global__ __launch_bounds__(256)
void gemm_tn(const float* __restrict__ A,
             const float* __restrict__ Bm,
             float* __restrict__ C,
             int M, int N, int K)
{
    __shared__ float As[BK][BM];
    __shared__ float Bs[BK][BN];

    const int tid = threadIdx.x;
    const int m0  = blockIdx.y * BM;
    const int n0  = blockIdx.x * BN;
    const int ty  = tid / (BN / TN);
    const int tx  = tid % (BN / TN);

    float tot[TM][TN];   // merged result across chunks
    float acc[TM][TN];   // current chunk partial
    #pragma unroll
    for (int i = 0; i < TM; i++)
        #pragma unroll
        for (int j = 0; j < TN; j++) {
            tot[i][j] = 0.0f;
            acc[i][j] = 0.0f;
        }

    constexpr int VPR = BK / 4;          // float4 vectors per row of a tile
    const int KCHUNK = K / NSPLIT;       // contiguous chunk length

    for (int k0 = 0; k0 < K; k0 += BK) {
        #pragma unroll
        for (int i = tid; i < BM * VPR; i += 256) {
            int r = i / VPR, c = i % VPR;
            float4 v = *reinterpret_cast<const float4*>(
                A + (size_t)(m0 + r) * K + k0 + c * 4);
            As[c * 4 + 0][r] = v.x;
            As[c * 4 + 1][r] = v.y;
            As[c * 4 + 2][r] = v.z;
            As[c * 4 + 3][r] = v.w;
        }
        #pragma unroll
        for (int i = tid; i < BN * VPR; i += 256) {
            int r = i / VPR, c = i % VPR;
            float4 v = *reinterpret_cast<const float4*>(
                Bm + (size_t)(n0 + r) * K + k0 + c * 4);
            Bs[c * 4 + 0][r] = v.x;
            Bs[c * 4 + 1][r] = v.y;
            Bs[c * 4 + 2][r] = v.z;
            Bs[c * 4 + 3][r] = v.w;
        }
        __syncthreads();

        #pragma unroll
        for (int k = 0; k < BK; k++) {
            float a[TM], b[TN];
            #pragma unroll
            for (int i = 0; i < TM; i += 4) {
                float4 v = *reinterpret_cast<const float4*>(&As[k][ty * TM + i]);
                a[i] = v.x; a[i+1] = v.y; a[i+2] = v.z; a[i+3] = v.w;
            }
            #pragma unroll
            for (int j = 0; j < TN; j += 4) {
                float4 v = *reinterpret_cast<const float4*>(&Bs[k][tx * TN + j]);
                b[j] = v.x; b[j+1] = v.y; b[j+2] = v.z; b[j+3] = v.w;
            }
            #pragma unroll
            for (int i = 0; i < TM; i++)
                #pragma unroll
                for (int j = 0; j < TN; j++)
                    acc[i][j] = fmaf(a[i], b[j], acc[i][j]);
        }
        __syncthreads();

        if (NSPLIT > 1 && ((k0 + BK) % KCHUNK == 0)) {
            #pragma unroll
            for (int i = 0; i < TM; i++)
                #pragma unroll
                for (int j = 0; j < TN; j++) {
                    tot[i][j] = __fadd_rn(tot[i][j], acc[i][j]);
                    acc[i][j] = 0.0f;
                }
        }
    }

    #pragma unroll
    for (int i = 0; i < TM; i++) {
        #pragma unroll
        for (int j = 0; j < TN; j += 4) {
            float4 v;
            if (NSPLIT > 1)
                v = make_float4(tot[i][j], tot[i][j+1], tot[i][j+2], tot[i][j+3]);
            else
                v = make_float4(acc[i][j], acc[i][j+1], acc[i][j+2], acc[i][j+3]);
            *reinterpret_cast<float4*>(
                C + (size_t)(m0 + ty * TM + i) * N + n0 + tx * TN + j) = v;
        }
    }
}

// ---------------------------------------------------------------------------
// GEMM2 fused with LIF2 epilogue.
//   O = s1 @ W2^T  (M=512, N=1024, K=2048), per-element single serial
//   ascending FMA chain (bitwise identical to R6's GEMM2 regardless of tile
//   shape), then per element: v2' = (v2 + O)*0.5; spike; hard reset; write
//   spike to out_com[(b*T + t)*OUT + o].
// Tiled BM=32, BN=64, BK=16, TM=2, TN=4, 256 threads -> grid 16x16 = 256 CTAs.
// ---------------------------------------------------------------------------
#define G2_BM 32
#define G2_BN 64
#define G2_BK 16
#define G2_TM 2
#define G2_TN 4

__global__ __launch_bounds__(256)
void gemm2_lif_kernel(const float* __restrict__ A,    // s1 [B, H]
                      const float* __restrict__ Bm,   // W2 [OUT, H]
                      int t,
                      float* __restrict__ out_com)
{
    __shared__ float As[G2_BK][G2_BM];
    __shared__ float Bs[G2_BK][G2_BN];

    const int tid = threadIdx.x;
    const int m0  = blockIdx.y * G2_BM;
    const int n0  = blockIdx.x * G2_BN;
    const int ty  = tid / (G2_BN / G2_TN);   // 0..15
    const int tx  = tid % (G2_BN / G2_TN);   // 0..15

    float acc[G2_TM][G2_TN];
    #pragma unroll
    for (int i = 0; i < G2_TM; i++)
        #pragma unroll
        for (int j = 0; j < G2_TN; j++)
            acc[i][j] = 0.0f;

    constexpr int VPR = G2_BK / 4;   // 4

    for (int k0 = 0; k0 < H_SZ; k0 += G2_BK) {
        // A tile: 32 rows x 4 vec -> 128 work items (first 128 threads)
        for (int i = tid; i < G2_BM * VPR; i += 256) {
            int r = i / VPR, c = i % VPR;
            float4 v = *reinterpret_cast<const float4*>(
                A + (size_t)(m0 + r) * H_SZ + k0 + c * 4);
            As[c * 4 + 0][r] = v.x;
            As[c * 4 + 1][r] = v.y;
            As[c * 4 + 2][r] = v.z;
            As[c * 4 + 3][r] = v.w;
        }
        // B tile: 64 rows x 4 vec -> 256 work items
        for (int i = tid; i < G2_BN * VPR; i += 256) {
            int r = i / VPR, c = i % VPR;
            float4 v = *reinterpret_cast<const float4*>(
                Bm + (size_t)(n0 + r) * H_SZ + k0 + c * 4);
            Bs[c * 4 + 0][r] = v.x;
            Bs[c * 4 + 1][r] = v.y;
            Bs[c * 4 + 2][r] = v.z;
            Bs[c * 4 + 3][r] = v.w;
        }
        __syncthreads();

        #pragma unroll
        for (int k = 0; k < G2_BK; k++) {
            float a[G2_TM], b[G2_TN];
            #pragma unroll
            for (int i = 0; i < G2_TM; i++)
                a[i] = As[k][ty * G2_TM + i];
            #pragma unroll
            for (int j = 0; j < G2_TN; j += 4) {
                float4 v = *reinterpret_cast<const float4*>(&Bs[k][tx * G2_TN + j]);
                b[j] = v.x; b[j+1] = v.y; b[j+2] = v.z; b[j+3] = v.w;
            }
            #pragma unroll
            for (int i = 0; i < G2_TM; i++)
                #pragma unroll
                for (int j = 0; j < G2_TN; j++)
                    acc[i][j] = fmaf(a[i], b[j], acc[i][j]);
        }
        __syncthreads();
    }

    // Fused LIF2 epilogue: each thread owns its (b, o) elements exclusively.
    #pragma unroll
    for (int i = 0; i < G2_TM; i++) {
        const int b = m0 + ty * G2_TM + i;
        #pragma unroll
        for (int j = 0; j < G2_TN; j++) {
            const int o = n0 + tx * G2_TN + j;
            const size_t vidx = (size_t)b * OUT_SZ + o;
            float v = g_v2[vidx];
            v = __fmul_rn(__fadd_rn(v, acc[i][j]), 0.5f);   // single rounding
            float s = (v >= 0.5f) ? 1.0f : 0.0f;
            out_com[((size_t)b * T_STEPS + t) * OUT_SZ + o] = s;
            g_v2[vidx] = (s != 0.0f) ? 0.0f : v;
        }
    }
}

// ---------------------------------------------------------------------------
// LIF step, layer 1: v' = round((v + inp) * 0.5); s = (v' >= 0.5); hard reset.
// ---------------------------------------------------------------------------
__global__ void lif1_kernel(int t, float* __restrict__ out_ch)
{
    size_t idx = (size_t)blockIdx.x * blockDim.x + threadIdx.x;
    if (idx >= (size_t)B_SZ * H_SZ) return;
    int b = (int)(idx / H_SZ);
    int h = (int)(idx % H_SZ);

    float inp = g_H[((size_t)b * T_STEPS + t) * H_SZ + h];
    float v   = g_v1[idx];
    v = __fmul_rn(__fadd_rn(v, inp), 0.5f);
    float s = (v >= 0.5f) ? 1.0f : 0.0f;
    g_s1[idx] = s;
    out_ch[((size_t)b * T_STEPS + t) * H_SZ + h] = s;
    g_v1[idx] = (s != 0.0f) ? 0.0f : v;
}

// ---------------------------------------------------------------------------
// kernel_launch: graph-capturable, allocation-free.
// Inputs: d_in[0]=x [B,T,F_IN] f32, d_in[1]=W1 [H,F_IN] f32, d_in[2]=W2 [OUT,H] f32
// Output: concat(com_spk [B,T,OUT], ch_spk [B,T,H], x [B,T,F_IN]) f32
// ---------------------------------------------------------------------------
extern "C" void kernel_launch(void* const* d_in, const int* in_sizes, int n_in,
                              void* d_out, int out_size)
{
    const float* x  = (const float*)d_in[0];
    const float* W1 = (const float*)d_in[1];
    const float* W2 = (const float*)d_in[2];
    float* out = (float*)d_out;

    const size_t COM_OFF = 0;
    const size_t CH_OFF  = (size_t)BT * OUT_SZ;                 // 8,388,608
    const size_t X_OFF   = CH_OFF + (size_t)BT * H_SZ;          // 25,165,824

    float* out_com = out + COM_OFF;
    float* out_ch  = out + CH_OFF;
    float* out_x   = out + X_OFF;

    // 0) zero membrane state
    {
        size_t n = (size_t)B_SZ * H_SZ;  // >= B*OUT
        init_state_kernel<<<(unsigned)((n + 255) / 256), 256>>>();
    }

    // 1) H = x @ W1^T over all timesteps — FROZEN accumulation order:
    //    NSPLIT=2 chunks of K=1024, serial ascending within, sequential merge.
    {
        float* g_H_p;
        cudaGetSymbolAddress((void**)&g_H_p, g_H);
        dim3 grid(H_SZ / 128, BT / 128);
        gemm_tn<128, 128, 16, 8, 8, 2><<<grid, 256>>>(x, W1, g_H_p, BT, H_SZ, F_IN);
    }

    float* g_s1_p;
    cudaGetSymbolAddress((void**)&g_s1_p, g_s1);

    // 2) sequential timesteps: lif1 -> fused gemm2+lif2
    for (int t = 0; t < T_STEPS; t++) {
        {
            size_t n = (size_t)B_SZ * H_SZ;
            lif1_kernel<<<(unsigned)((n + 255) / 256), 256>>>(t, out_ch);
        }
        {
            dim3 grid(OUT_SZ / G2_BN, B_SZ / G2_BM);   // 16 x 16 = 256 CTAs
            gemm2_lif_kernel<<<grid, 256>>>(g_s1_p, W2, t, out_com);
        }
    }

    // 3) passthrough x
    cudaMemcpyAsync(out_x, x, (size_t)BT * F_IN * sizeof(float),
                    cudaMemcpyDeviceToDevice, 0);

    (void)in_sizes; (void)n_in; (void)out_size;
}

// round 8
// speedup vs baseline: 1.6942x; 1.6942x over previous
#include <cuda_runtime.h>
#include <cstddef>

// Problem constants (fixed shapes from reference setup_inputs)
#define T_STEPS 16
#define B_SZ    512
#define F_IN    2048
#define H_SZ    2048
#define OUT_SZ  1024
#define BT      (B_SZ * T_STEPS)   // 8192

// Scratch (device globals: allocation-free per harness rules)
__device__ float g_H  [ (size_t)BT  * H_SZ   ];   // 64 MB: fc1 pre-activations, all t
__device__ float g_v1 [ (size_t)B_SZ * H_SZ  ];   // membrane lif1
__device__ float g_v2 [ (size_t)B_SZ * OUT_SZ];   // membrane lif_out
__device__ float g_W2T[ (size_t)H_SZ * OUT_SZ];   // 8 MB: W2 transposed [H, OUT]
__device__ int   g_idx[ (size_t)B_SZ * H_SZ  ];   // per-row active-k lists (ascending)
__device__ int   g_cnt[ B_SZ ];                   // per-row active counts

// ---------------------------------------------------------------------------
// init: zero membranes
// ---------------------------------------------------------------------------
__global__ void init_state_kernel() {
    size_t i = (size_t)blockIdx.x * blockDim.x + threadIdx.x;
    size_t n1 = (size_t)B_SZ * H_SZ;
    size_t n2 = (size_t)B_SZ * OUT_SZ;
    if (i < n1) g_v1[i] = 0.0f;
    if (i < n2) g_v2[i] = 0.0f;
}

// ---------------------------------------------------------------------------
// Transpose W2 [OUT, H] -> W2T [H, OUT].  32x32 smem tiles.
// ---------------------------------------------------------------------------
__global__ void transpose_w2_kernel(const float* __restrict__ W2)
{
    __shared__ float tile[32][33];
    int o0 = blockIdx.y * 32;      // row block in W2 (OUT dim)
    int k0 = blockIdx.x * 32;      // col block in W2 (H dim)
    int tx = threadIdx.x, ty = threadIdx.y;   // 32 x 8

    #pragma unroll
    for (int r = 0; r < 32; r += 8)
        tile[ty + r][tx] = W2[(size_t)(o0 + ty + r) * H_SZ + k0 + tx];
    __syncthreads();
    #pragma unroll
    for (int r = 0; r < 32; r += 8)
        g_W2T[(size_t)(k0 + ty + r) * OUT_SZ + o0 + tx] = tile[tx][ty + r];
}

// ---------------------------------------------------------------------------
// GEMM1 (FROZEN — bitwise contract with reference, established R6):
// kc-blocked accumulation: NSPLIT contiguous chunks, each serial ascending
// FMA chain from zero, sequential merge.
// ---------------------------------------------------------------------------
template<int BM, int BN, int BK, int TM, int TN, int NSPLIT>
__global__ __launch_bounds__(256)
void gemm_tn(const float* __restrict__ A,
             const float* __restrict__ Bm,
             float* __restrict__ C,
             int M, int N, int K)
{
    __shared__ float As[BK][BM];
    __shared__ float Bs[BK][BN];

    const int tid = threadIdx.x;
    const int m0  = blockIdx.y * BM;
    const int n0  = blockIdx.x * BN;
    const int ty  = tid / (BN / TN);
    const int tx  = tid % (BN / TN);

    float tot[TM][TN];
    float acc[TM][TN];
    #pragma unroll
    for (int i = 0; i < TM; i++)
        #pragma unroll
        for (int j = 0; j < TN; j++) {
            tot[i][j] = 0.0f;
            acc[i][j] = 0.0f;
        }

    constexpr int VPR = BK / 4;
    const int KCHUNK = K / NSPLIT;

    for (int k0 = 0; k0 < K; k0 += BK) {
        #pragma unroll
        for (int i = tid; i < BM * VPR; i += 256) {
            int r = i / VPR, c = i % VPR;
            float4 v = *reinterpret_cast<const float4*>(
                A + (size_t)(m0 + r) * K + k0 + c * 4);
            As[c * 4 + 0][r] = v.x;
            As[c * 4 + 1][r] = v.y;
            As[c * 4 + 2][r] = v.z;
            As[c * 4 + 3][r] = v.w;
        }
        #pragma unroll
        for (int i = tid; i < BN * VPR; i += 256) {
            int r = i / VPR, c = i % VPR;
            float4 v = *reinterpret_cast<const float4*>(
                Bm + (size_t)(n0 + r) * K + k0 + c * 4);
            Bs[c * 4 + 0][r] = v.x;
            Bs[c * 4 + 1][r] = v.y;
            Bs[c * 4 + 2][r] = v.z;
            Bs[c * 4 + 3][r] = v.w;
        }
        __syncthreads();

        #pragma unroll
        for (int k = 0; k < BK; k++) {
            float a[TM], b[TN];
            #pragma unroll
            for (int i = 0; i < TM; i += 4) {
                float4 v = *reinterpret_cast<const float4*>(&As[k][ty * TM + i]);
                a[i] = v.x; a[i+1] = v.y; a[i+2] = v.z; a[i+3] = v.w;
            }
            #pragma unroll
            for (int j = 0; j < TN; j += 4) {
                float4 v = *reinterpret_cast<const float4*>(&Bs[k][tx * TN + j]);
                b[j] = v.x; b[j+1] = v.y; b[j+2] = v.z; b[j+3] = v.w;
            }
            #pragma unroll
            for (int i = 0; i < TM; i++)
                #pragma unroll
                for (int j = 0; j < TN; j++)
                    acc[i][j] = fmaf(a[i], b[j], acc[i][j]);
        }
        __syncthreads();

        if (NSPLIT > 1 && ((k0 + BK) % KCHUNK == 0)) {
            #pragma unroll
            for (int i = 0; i < TM; i++)
                #pragma unroll
                for (int j = 0; j < TN; j++) {
                    tot[i][j] = __fadd_rn(tot[i][j], acc[i][j]);
                    acc[i][j] = 0.0f;
                }
        }
    }

    #pragma unroll
    for (int i = 0; i < TM; i++) {
        #pragma unroll
        for (int j = 0; j < TN; j += 4) {
            float4 v;
            if (NSPLIT > 1)
                v = make_float4(tot[i][j], tot[i][j+1], tot[i][j+2], tot[i][j+3]);
            else
                v = make_float4(acc[i][j], acc[i][j+1], acc[i][j+2], acc[i][j+3]);
            *reinterpret_cast<float4*>(
                C + (size_t)(m0 + ty * TM + i) * N + n0 + tx * TN + j) = v;
        }
    }
}

// ---------------------------------------------------------------------------
// LIF1 + ordered compaction. One CTA (256 threads) per batch row b.
// Each thread owns the contiguous k-chunk [tid*8, tid*8+8): LIF update,
// spike write to out_ch, then block-exclusive-scan of per-thread spike
// counts -> indices of spiking k written to g_idx[b] in ASCENDING k order.
// ---------------------------------------------------------------------------
__global__ __launch_bounds__(256)
void lif1_compact_kernel(int t, float* __restrict__ out_ch)
{
    const int b   = blockIdx.x;
    const int tid = threadIdx.x;
    const int PER = H_SZ / 256;   // 8

    const size_t hbase = ((size_t)b * T_STEPS + t) * H_SZ + (size_t)tid * PER;
    const size_t vbase = (size_t)b * H_SZ + (size_t)tid * PER;

    float h[PER], v[PER];
    #pragma unroll
    for (int j = 0; j < PER; j += 4) {
        float4 hv = *reinterpret_cast<const float4*>(&g_H[hbase + j]);
        h[j] = hv.x; h[j+1] = hv.y; h[j+2] = hv.z; h[j+3] = hv.w;
        float4 vv = *reinterpret_cast<const float4*>(&g_v1[vbase + j]);
        v[j] = vv.x; v[j+1] = vv.y; v[j+2] = vv.z; v[j+3] = vv.w;
    }

    float s[PER];
    int cnt = 0;
    #pragma unroll
    for (int j = 0; j < PER; j++) {
        float nv = __fmul_rn(__fadd_rn(v[j], h[j]), 0.5f);   // single rounding
        s[j] = (nv >= 0.5f) ? 1.0f : 0.0f;
        v[j] = (s[j] != 0.0f) ? 0.0f : nv;
        cnt += (s[j] != 0.0f) ? 1 : 0;
    }

    // write spikes + membranes back
    #pragma unroll
    for (int j = 0; j < PER; j += 4) {
        *reinterpret_cast<float4*>(&out_ch[hbase + j]) =
            make_float4(s[j], s[j+1], s[j+2], s[j+3]);
        *reinterpret_cast<float4*>(&g_v1[vbase + j]) =
            make_float4(v[j], v[j+1], v[j+2], v[j+3]);
    }

    // block inclusive scan of counts (Hillis-Steele)
    __shared__ int sc[256];
    sc[tid] = cnt;
    __syncthreads();
    #pragma unroll
    for (int off = 1; off < 256; off <<= 1) {
        int add = (tid >= off) ? sc[tid - off] : 0;
        __syncthreads();
        sc[tid] += add;
        __syncthreads();
    }
    int pos = sc[tid] - cnt;   // exclusive prefix

    int* idx = g_idx + (size_t)b * H_SZ;
    #pragma unroll
    for (int j = 0; j < PER; j++)
        if (s[j] != 0.0f)
            idx[pos++] = tid * PER + j;

    if (tid == 255) g_cnt[b] = sc[255];
}

// ---------------------------------------------------------------------------
// Sparse GEMM2 + LIF2. One CTA (256 threads) per batch row b.
// O[b, o] = sum over active k (ASCENDING) of W2T[k, o] — bitwise identical
// to the dense serial ascending FMA chain, since fma(0,w,acc)==acc and
// fma(1,w,acc)==acc+w exactly. Each thread owns o = tid*4 .. tid*4+3.
// Fused LIF2 epilogue.
// ---------------------------------------------------------------------------
__global__ __launch_bounds__(256)
void spmm_lif2_kernel(int t, float* __restrict__ out_com)
{
    const int b   = blockIdx.x;
    const int tid = threadIdx.x;
    const int cnt = g_cnt[b];
    const int* __restrict__ idx = g_idx + (size_t)b * H_SZ;
    const int o = tid * 4;

    float a0 = 0.0f, a1 = 0.0f, a2 = 0.0f, a3 = 0.0f;

    __shared__ int sk[256];
    for (int base = 0; base < cnt; base += 256) {
        const int n = min(256, cnt - base);
        if (tid < n) sk[tid] = idx[base + tid];
        __syncthreads();
        #pragma unroll 4
        for (int i = 0; i < n; i++) {
            const int k = sk[i];
            float4 w = *reinterpret_cast<const float4*>(
                &g_W2T[(size_t)k * OUT_SZ + o]);
            a0 = __fadd_rn(a0, w.x);
            a1 = __fadd_rn(a1, w.y);
            a2 = __fadd_rn(a2, w.z);
            a3 = __fadd_rn(a3, w.w);
        }
        __syncthreads();
    }

    // LIF2 epilogue
    const size_t vbase = (size_t)b * OUT_SZ + o;
    float4 vv = *reinterpret_cast<const float4*>(&g_v2[vbase]);
    float acc[4] = {a0, a1, a2, a3};
    float vin[4] = {vv.x, vv.y, vv.z, vv.w};
    float sp[4], vout[4];
    #pragma unroll
    for (int j = 0; j < 4; j++) {
        float nv = __fmul_rn(__fadd_rn(vin[j], acc[j]), 0.5f);
        sp[j]   = (nv >= 0.5f) ? 1.0f : 0.0f;
        vout[j] = (sp[j] != 0.0f) ? 0.0f : nv;
    }
    *reinterpret_cast<float4*>(
        &out_com[((size_t)b * T_STEPS + t) * OUT_SZ + o]) =
        make_float4(sp[0], sp[1], sp[2], sp[3]);
    *reinterpret_cast<float4*>(&g_v2[vbase]) =
        make_float4(vout[0], vout[1], vout[2], vout[3]);
}

// ---------------------------------------------------------------------------
// kernel_launch: graph-capturable, allocation-free.
// Inputs: d_in[0]=x [B,T,F_IN] f32, d_in[1]=W1 [H,F_IN] f32, d_in[2]=W2 [OUT,H] f32
// Output: concat(com_spk [B,T,OUT], ch_spk [B,T,H], x [B,T,F_IN]) f32
// ---------------------------------------------------------------------------
extern "C" void kernel_launch(void* const* d_in, const int* in_sizes, int n_in,
                              void* d_out, int out_size)
{
    const float* x  = (const float*)d_in[0];
    const float* W1 = (const float*)d_in[1];
    const float* W2 = (const float*)d_in[2];
    float* out = (float*)d_out;

    const size_t COM_OFF = 0;
    const size_t CH_OFF  = (size_t)BT * OUT_SZ;
    const size_t X_OFF   = CH_OFF + (size_t)BT * H_SZ;

    float* out_com = out + COM_OFF;
    float* out_ch  = out + CH_OFF;
    float* out_x   = out + X_OFF;

    // 0) zero membranes + transpose W2
    {
        size_t n = (size_t)B_SZ * H_SZ;
        init_state_kernel<<<(unsigned)((n + 255) / 256), 256>>>();
        dim3 tgrid(H_SZ / 32, OUT_SZ / 32);
        transpose_w2_kernel<<<tgrid, dim3(32, 8)>>>(W2);
    }

    // 1) H = x @ W1^T over all timesteps — FROZEN accumulation order
    //    (NSPLIT=2 chunks of 1024, serial ascending within, sequential merge).
    {
        float* g_H_p;
        cudaGetSymbolAddress((void**)&g_H_p, g_H);
        dim3 grid(H_SZ / 128, BT / 128);
        gemm_tn<128, 128, 16, 8, 8, 2><<<grid, 256>>>(x, W1, g_H_p, BT, H_SZ, F_IN);
    }

    // 2) sequential timesteps: fused lif1+compact -> sparse gemm2+lif2
    for (int t = 0; t < T_STEPS; t++) {
        lif1_compact_kernel<<<B_SZ, 256>>>(t, out_ch);
        spmm_lif2_kernel<<<B_SZ, 256>>>(t, out_com);
    }

    // 3) passthrough x
    cudaMemcpyAsync(out_x, x, (size_t)BT * F_IN * sizeof(float),
                    cudaMemcpyDeviceToDevice, 0);

    (void)in_sizes; (void)n_in; (void)out_size;
}

// round 9
// speedup vs baseline: 1.7538x; 1.0352x over previous
#include <cuda_runtime.h>
#include <cstddef>

// Problem constants (fixed shapes from reference setup_inputs)
#define T_STEPS 16
#define B_SZ    512
#define F_IN    2048
#define H_SZ    2048
#define OUT_SZ  1024
#define BT      (B_SZ * T_STEPS)   // 8192

// Scratch (device globals: allocation-free per harness rules)
__device__ float g_H  [ (size_t)BT  * H_SZ   ];   // 64 MB: fc1 pre-activations, all t
__device__ float g_v1 [ (size_t)B_SZ * H_SZ  ];   // membrane lif1
__device__ float g_v2 [ (size_t)B_SZ * OUT_SZ];   // membrane lif_out
__device__ float g_W2T[ (size_t)H_SZ * OUT_SZ];   // 8 MB: W2 transposed [H, OUT]
__device__ int   g_idx[ (size_t)B_SZ * H_SZ  ];   // per-row active-k lists (ascending)
__device__ int   g_cnt[ B_SZ ];                   // per-row active counts

// ---------------------------------------------------------------------------
// init: zero membranes
// ---------------------------------------------------------------------------
__global__ void init_state_kernel() {
    size_t i = (size_t)blockIdx.x * blockDim.x + threadIdx.x;
    size_t n1 = (size_t)B_SZ * H_SZ;
    size_t n2 = (size_t)B_SZ * OUT_SZ;
    if (i < n1) g_v1[i] = 0.0f;
    if (i < n2) g_v2[i] = 0.0f;
}

// ---------------------------------------------------------------------------
// Transpose W2 [OUT, H] -> W2T [H, OUT].  32x32 smem tiles.
// ---------------------------------------------------------------------------
__global__ void transpose_w2_kernel(const float* __restrict__ W2)
{
    __shared__ float tile[32][33];
    int o0 = blockIdx.y * 32;
    int k0 = blockIdx.x * 32;
    int tx = threadIdx.x, ty = threadIdx.y;   // 32 x 8

    #pragma unroll
    for (int r = 0; r < 32; r += 8)
        tile[ty + r][tx] = W2[(size_t)(o0 + ty + r) * H_SZ + k0 + tx];
    __syncthreads();
    #pragma unroll
    for (int r = 0; r < 32; r += 8)
        g_W2T[(size_t)(k0 + ty + r) * OUT_SZ + o0 + tx] = tile[tx][ty + r];
}

// ---------------------------------------------------------------------------
// GEMM1, software-pipelined with double-buffered smem.
// H = x @ W1^T : [8192, 2048] x [2048, 2048]^T.
// ACCUMULATION ORDER (FROZEN bitwise contract, established R6):
//   per output element: 2 contiguous K-chunks of 1024, each a serial
//   ascending FMA chain from zero, chunk partials merged sequentially.
// Pipelining changes ONLY load scheduling, never arithmetic order.
// BM=BN=128, BK=16, TM=TN=8, 256 threads. Grid: (N/128, M/128) = (16, 64).
// ---------------------------------------------------------------------------
#define G1_BM 128
#define G1_BN 128
#define G1_BK 16
#define G1_TM 8
#define G1_TN 8
#define G1_VPR (G1_BK / 4)           // 4 float4 per tile row
#define G1_NT  (F_IN / G1_BK)        // 128 k-tiles
#define G1_MERGE_TILE (1024 / G1_BK) // merge every 64 tiles (kc = 1024)

__global__ __launch_bounds__(256)
void gemm1_pipe_kernel(const float* __restrict__ A,    // x   [BT, F_IN]
                       const float* __restrict__ Bm,   // W1  [H, F_IN]
                       float* __restrict__ C)          // g_H [BT, H]
{
    __shared__ float As[2][G1_BK][G1_BM];
    __shared__ float Bs[2][G1_BK][G1_BN];

    const int tid = threadIdx.x;
    const int m0  = blockIdx.y * G1_BM;
    const int n0  = blockIdx.x * G1_BN;
    const int ty  = tid / (G1_BN / G1_TN);
    const int tx  = tid % (G1_BN / G1_TN);

    // Per-thread staging registers for the next tile (2 float4 each matrix)
    const int r0 = tid >> 2;               // row for item 0 (i = tid)
    const int c0 = tid & 3;                // vec-col for item 0
    const int r1 = (tid + 256) >> 2;       // row for item 1
    const int c1 = (tid + 256) & 3;

    const float* Arow0 = A  + (size_t)(m0 + r0) * F_IN + c0 * 4;
    const float* Arow1 = A  + (size_t)(m0 + r1) * F_IN + c1 * 4;
    const float* Brow0 = Bm + (size_t)(n0 + r0) * F_IN + c0 * 4;
    const float* Brow1 = Bm + (size_t)(n0 + r1) * F_IN + c1 * 4;

    float tot[G1_TM][G1_TN];
    float acc[G1_TM][G1_TN];
    #pragma unroll
    for (int i = 0; i < G1_TM; i++)
        #pragma unroll
        for (int j = 0; j < G1_TN; j++) {
            tot[i][j] = 0.0f;
            acc[i][j] = 0.0f;
        }

    float4 ra0, ra1, rb0, rb1;

    // Prologue: load tile 0, store to buffer 0
    ra0 = *reinterpret_cast<const float4*>(Arow0);
    ra1 = *reinterpret_cast<const float4*>(Arow1);
    rb0 = *reinterpret_cast<const float4*>(Brow0);
    rb1 = *reinterpret_cast<const float4*>(Brow1);
    {
        As[0][c0*4+0][r0] = ra0.x; As[0][c0*4+1][r0] = ra0.y;
        As[0][c0*4+2][r0] = ra0.z; As[0][c0*4+3][r0] = ra0.w;
        As[0][c1*4+0][r1] = ra1.x; As[0][c1*4+1][r1] = ra1.y;
        As[0][c1*4+2][r1] = ra1.z; As[0][c1*4+3][r1] = ra1.w;
        Bs[0][c0*4+0][r0] = rb0.x; Bs[0][c0*4+1][r0] = rb0.y;
        Bs[0][c0*4+2][r0] = rb0.z; Bs[0][c0*4+3][r0] = rb0.w;
        Bs[0][c1*4+0][r1] = rb1.x; Bs[0][c1*4+1][r1] = rb1.y;
        Bs[0][c1*4+2][r1] = rb1.z; Bs[0][c1*4+3][r1] = rb1.w;
    }
    __syncthreads();

    for (int kt = 0; kt < G1_NT; kt++) {
        const int buf = kt & 1;

        // Issue next tile's global loads early (overlap with compute)
        if (kt + 1 < G1_NT) {
            const int koff = (kt + 1) * G1_BK;
            ra0 = *reinterpret_cast<const float4*>(Arow0 + koff);
            ra1 = *reinterpret_cast<const float4*>(Arow1 + koff);
            rb0 = *reinterpret_cast<const float4*>(Brow0 + koff);
            rb1 = *reinterpret_cast<const float4*>(Brow1 + koff);
        }

        // Compute current tile (serial ascending k — frozen order)
        #pragma unroll
        for (int k = 0; k < G1_BK; k++) {
            float a[G1_TM], b[G1_TN];
            #pragma unroll
            for (int i = 0; i < G1_TM; i += 4) {
                float4 v = *reinterpret_cast<const float4*>(&As[buf][k][ty * G1_TM + i]);
                a[i] = v.x; a[i+1] = v.y; a[i+2] = v.z; a[i+3] = v.w;
            }
            #pragma unroll
            for (int j = 0; j < G1_TN; j += 4) {
                float4 v = *reinterpret_cast<const float4*>(&Bs[buf][k][tx * G1_TN + j]);
                b[j] = v.x; b[j+1] = v.y; b[j+2] = v.z; b[j+3] = v.w;
            }
            #pragma unroll
            for (int i = 0; i < G1_TM; i++)
                #pragma unroll
                for (int j = 0; j < G1_TN; j++)
                    acc[i][j] = fmaf(a[i], b[j], acc[i][j]);
        }

        // Stage next tile into the other buffer (safe: nobody reads it now)
        if (kt + 1 < G1_NT) {
            const int nb = 1 - buf;
            As[nb][c0*4+0][r0] = ra0.x; As[nb][c0*4+1][r0] = ra0.y;
            As[nb][c0*4+2][r0] = ra0.z; As[nb][c0*4+3][r0] = ra0.w;
            As[nb][c1*4+0][r1] = ra1.x; As[nb][c1*4+1][r1] = ra1.y;
            As[nb][c1*4+2][r1] = ra1.z; As[nb][c1*4+3][r1] = ra1.w;
            Bs[nb][c0*4+0][r0] = rb0.x; Bs[nb][c0*4+1][r0] = rb0.y;
            Bs[nb][c0*4+2][r0] = rb0.z; Bs[nb][c0*4+3][r0] = rb0.w;
            Bs[nb][c1*4+0][r1] = rb1.x; Bs[nb][c1*4+1][r1] = rb1.y;
            Bs[nb][c1*4+2][r1] = rb1.z; Bs[nb][c1*4+3][r1] = rb1.w;
        }
        __syncthreads();

        // kc-chunk boundary (kc = 1024): sequential merge, reset chunk acc
        if (((kt + 1) % G1_MERGE_TILE) == 0) {
            #pragma unroll
            for (int i = 0; i < G1_TM; i++)
                #pragma unroll
                for (int j = 0; j < G1_TN; j++) {
                    tot[i][j] = __fadd_rn(tot[i][j], acc[i][j]);
                    acc[i][j] = 0.0f;
                }
        }
    }

    #pragma unroll
    for (int i = 0; i < G1_TM; i++) {
        #pragma unroll
        for (int j = 0; j < G1_TN; j += 4) {
            float4 v = make_float4(tot[i][j], tot[i][j+1], tot[i][j+2], tot[i][j+3]);
            *reinterpret_cast<float4*>(
                C + (size_t)(m0 + ty * G1_TM + i) * H_SZ + n0 + tx * G1_TN + j) = v;
        }
    }
}

// ---------------------------------------------------------------------------
// LIF1 + ordered compaction. One CTA (256 threads) per batch row b.
// ---------------------------------------------------------------------------
__global__ __launch_bounds__(256)
void lif1_compact_kernel(int t, float* __restrict__ out_ch)
{
    const int b   = blockIdx.x;
    const int tid = threadIdx.x;
    const int PER = H_SZ / 256;   // 8

    const size_t hbase = ((size_t)b * T_STEPS + t) * H_SZ + (size_t)tid * PER;
    const size_t vbase = (size_t)b * H_SZ + (size_t)tid * PER;

    float h[PER], v[PER];
    #pragma unroll
    for (int j = 0; j < PER; j += 4) {
        float4 hv = *reinterpret_cast<const float4*>(&g_H[hbase + j]);
        h[j] = hv.x; h[j+1] = hv.y; h[j+2] = hv.z; h[j+3] = hv.w;
        float4 vv = *reinterpret_cast<const float4*>(&g_v1[vbase + j]);
        v[j] = vv.x; v[j+1] = vv.y; v[j+2] = vv.z; v[j+3] = vv.w;
    }

    float s[PER];
    int cnt = 0;
    #pragma unroll
    for (int j = 0; j < PER; j++) {
        float nv = __fmul_rn(__fadd_rn(v[j], h[j]), 0.5f);   // single rounding
        s[j] = (nv >= 0.5f) ? 1.0f : 0.0f;
        v[j] = (s[j] != 0.0f) ? 0.0f : nv;
        cnt += (s[j] != 0.0f) ? 1 : 0;
    }

    #pragma unroll
    for (int j = 0; j < PER; j += 4) {
        *reinterpret_cast<float4*>(&out_ch[hbase + j]) =
            make_float4(s[j], s[j+1], s[j+2], s[j+3]);
        *reinterpret_cast<float4*>(&g_v1[vbase + j]) =
            make_float4(v[j], v[j+1], v[j+2], v[j+3]);
    }

    // block inclusive scan of counts
    __shared__ int sc[256];
    sc[tid] = cnt;
    __syncthreads();
    #pragma unroll
    for (int off = 1; off < 256; off <<= 1) {
        int add = (tid >= off) ? sc[tid - off] : 0;
        __syncthreads();
        sc[tid] += add;
        __syncthreads();
    }
    int pos = sc[tid] - cnt;   // exclusive prefix

    int* idx = g_idx + (size_t)b * H_SZ;
    #pragma unroll
    for (int j = 0; j < PER; j++)
        if (s[j] != 0.0f)
            idx[pos++] = tid * PER + j;

    if (tid == 255) g_cnt[b] = sc[255];
}

// ---------------------------------------------------------------------------
// Sparse GEMM2 + LIF2. One CTA (256 threads) per batch row b.
// Sparse ascending-k sum == dense serial ascending FMA chain, bitwise.
// ---------------------------------------------------------------------------
__global__ __launch_bounds__(256)
void spmm_lif2_kernel(int t, float* __restrict__ out_com)
{
    const int b   = blockIdx.x;
    const int tid = threadIdx.x;
    const int cnt = g_cnt[b];
    const int* __restrict__ idx = g_idx + (size_t)b * H_SZ;
    const int o = tid * 4;

    float a0 = 0.0f, a1 = 0.0f, a2 = 0.0f, a3 = 0.0f;

    __shared__ int sk[256];
    for (int base = 0; base < cnt; base += 256) {
        const int n = min(256, cnt - base);
        if (tid < n) sk[tid] = idx[base + tid];
        __syncthreads();
        #pragma unroll 4
        for (int i = 0; i < n; i++) {
            const int k = sk[i];
            float4 w = *reinterpret_cast<const float4*>(
                &g_W2T[(size_t)k * OUT_SZ + o]);
            a0 = __fadd_rn(a0, w.x);
            a1 = __fadd_rn(a1, w.y);
            a2 = __fadd_rn(a2, w.z);
            a3 = __fadd_rn(a3, w.w);
        }
        __syncthreads();
    }

    const size_t vbase = (size_t)b * OUT_SZ + o;
    float4 vv = *reinterpret_cast<const float4*>(&g_v2[vbase]);
    float acc[4] = {a0, a1, a2, a3};
    float vin[4] = {vv.x, vv.y, vv.z, vv.w};
    float sp[4], vout[4];
    #pragma unroll
    for (int j = 0; j < 4; j++) {
        float nv = __fmul_rn(__fadd_rn(vin[j], acc[j]), 0.5f);
        sp[j]   = (nv >= 0.5f) ? 1.0f : 0.0f;
        vout[j] = (sp[j] != 0.0f) ? 0.0f : nv;
    }
    *reinterpret_cast<float4*>(
        &out_com[((size_t)b * T_STEPS + t) * OUT_SZ + o]) =
        make_float4(sp[0], sp[1], sp[2], sp[3]);
    *reinterpret_cast<float4*>(&g_v2[vbase]) =
        make_float4(vout[0], vout[1], vout[2], vout[3]);
}

// ---------------------------------------------------------------------------
// kernel_launch: graph-capturable, allocation-free.
// Inputs: d_in[0]=x [B,T,F_IN] f32, d_in[1]=W1 [H,F_IN] f32, d_in[2]=W2 [OUT,H] f32
// Output: concat(com_spk [B,T,OUT], ch_spk [B,T,H], x [B,T,F_IN]) f32
// ---------------------------------------------------------------------------
extern "C" void kernel_launch(void* const* d_in, const int* in_sizes, int n_in,
                              void* d_out, int out_size)
{
    const float* x  = (const float*)d_in[0];
    const float* W1 = (const float*)d_in[1];
    const float* W2 = (const float*)d_in[2];
    float* out = (float*)d_out;

    const size_t COM_OFF = 0;
    const size_t CH_OFF  = (size_t)BT * OUT_SZ;
    const size_t X_OFF   = CH_OFF + (size_t)BT * H_SZ;

    float* out_com = out + COM_OFF;
    float* out_ch  = out + CH_OFF;
    float* out_x   = out + X_OFF;

    // 0) zero membranes + transpose W2
    {
        size_t n = (size_t)B_SZ * H_SZ;
        init_state_kernel<<<(unsigned)((n + 255) / 256), 256>>>();
        dim3 tgrid(H_SZ / 32, OUT_SZ / 32);
        transpose_w2_kernel<<<tgrid, dim3(32, 8)>>>(W2);
    }

    // 1) H = x @ W1^T over all timesteps — pipelined, frozen accumulation order
    {
        float* g_H_p;
        cudaGetSymbolAddress((void**)&g_H_p, g_H);
        dim3 grid(H_SZ / G1_BN, BT / G1_BM);   // (16, 64)
        gemm1_pipe_kernel<<<grid, 256>>>(x, W1, g_H_p);
    }

    // 2) sequential timesteps: fused lif1+compact -> sparse gemm2+lif2
    for (int t = 0; t < T_STEPS; t++) {
        lif1_compact_kernel<<<B_SZ, 256>>>(t, out_ch);
        spmm_lif2_kernel<<<B_SZ, 256>>>(t, out_com);
    }

    // 3) passthrough x
    cudaMemcpyAsync(out_x, x, (size_t)BT * F_IN * sizeof(float),
                    cudaMemcpyDeviceToDevice, 0);

    (void)in_sizes; (void)n_in; (void)out_size;
}

// round 10
// speedup vs baseline: 1.9167x; 1.0929x over previous
#include <cuda_runtime.h>
#include <cstddef>

// Problem constants (fixed shapes from reference setup_inputs)
#define T_STEPS 16
#define B_SZ    512
#define F_IN    2048
#define H_SZ    2048
#define OUT_SZ  1024
#define BT      (B_SZ * T_STEPS)   // 8192

// Scratch (device globals: allocation-free per harness rules)
__device__ float g_H  [ (size_t)BT  * H_SZ   ];   // 64 MB: fc1 pre-activations, all t
__device__ float g_v1 [ (size_t)B_SZ * H_SZ  ];   // membrane lif1
__device__ float g_v2 [ (size_t)B_SZ * OUT_SZ];   // membrane lif_out
__device__ float g_W2T[ (size_t)H_SZ * OUT_SZ];   // 8 MB: W2 transposed [H, OUT]

// ---------------------------------------------------------------------------
// init: zero membranes
// ---------------------------------------------------------------------------
__global__ void init_state_kernel() {
    size_t i = (size_t)blockIdx.x * blockDim.x + threadIdx.x;
    size_t n1 = (size_t)B_SZ * H_SZ;
    size_t n2 = (size_t)B_SZ * OUT_SZ;
    if (i < n1) g_v1[i] = 0.0f;
    if (i < n2) g_v2[i] = 0.0f;
}

// ---------------------------------------------------------------------------
// Transpose W2 [OUT, H] -> W2T [H, OUT].  32x32 smem tiles.
// ---------------------------------------------------------------------------
__global__ void transpose_w2_kernel(const float* __restrict__ W2)
{
    __shared__ float tile[32][33];
    int o0 = blockIdx.y * 32;
    int k0 = blockIdx.x * 32;
    int tx = threadIdx.x, ty = threadIdx.y;   // 32 x 8

    #pragma unroll
    for (int r = 0; r < 32; r += 8)
        tile[ty + r][tx] = W2[(size_t)(o0 + ty + r) * H_SZ + k0 + tx];
    __syncthreads();
    #pragma unroll
    for (int r = 0; r < 32; r += 8)
        g_W2T[(size_t)(k0 + ty + r) * OUT_SZ + o0 + tx] = tile[tx][ty + r];
}

// ---------------------------------------------------------------------------
// GEMM1 phase kernel (H = x @ W1^T, one kc=1024 chunk per launch).
// ACCUMULATION CONTRACT (frozen, R6): per element, 2 contiguous chunks of
// 1024, each a serial ascending FMA chain from zero, merged sequentially.
//   Phase A (ACCUM=false): C  = chain(K[0:1024])
//   Phase B (ACCUM=true):  C  = __fadd_rn(C, chain(K[1024:2048]))  — the
//   one-rounding sequential merge, bitwise identical to the fused form.
// Register relief vs single-kernel version: only acc[64] is live -> ~110
// regs -> 2 CTAs/SM.  Software-pipelined via register staging + double
// buffer (load scheduling only; arithmetic order untouched).
// BM=BN=128, BK=16, TM=TN=8, 256 threads. Grid (16, 64).
// ---------------------------------------------------------------------------
#define G1_BM 128
#define G1_BN 128
#define G1_BK 16
#define G1_TM 8
#define G1_TN 8
#define G1_KC 1024
#define G1_NT (G1_KC / G1_BK)   // 64 tiles per phase

template<bool ACCUM>
__global__ __launch_bounds__(256)
void gemm1_phase_kernel(const float* __restrict__ A,    // x   [BT, F_IN]
                        const float* __restrict__ Bm,   // W1  [H, F_IN]
                        float* __restrict__ C,          // g_H [BT, H]
                        int k_base)
{
    __shared__ float As[2][G1_BK][G1_BM];
    __shared__ float Bs[2][G1_BK][G1_BN];

    const int tid = threadIdx.x;
    const int m0  = blockIdx.y * G1_BM;
    const int n0  = blockIdx.x * G1_BN;
    const int ty  = tid / (G1_BN / G1_TN);
    const int tx  = tid % (G1_BN / G1_TN);

    const int r0 = tid >> 2;
    const int c0 = tid & 3;
    const int r1 = (tid + 256) >> 2;
    const int c1 = (tid + 256) & 3;

    const float* Arow0 = A  + (size_t)(m0 + r0) * F_IN + k_base + c0 * 4;
    const float* Arow1 = A  + (size_t)(m0 + r1) * F_IN + k_base + c1 * 4;
    const float* Brow0 = Bm + (size_t)(n0 + r0) * F_IN + k_base + c0 * 4;
    const float* Brow1 = Bm + (size_t)(n0 + r1) * F_IN + k_base + c1 * 4;

    float acc[G1_TM][G1_TN];
    #pragma unroll
    for (int i = 0; i < G1_TM; i++)
        #pragma unroll
        for (int j = 0; j < G1_TN; j++)
            acc[i][j] = 0.0f;

    float4 ra0, ra1, rb0, rb1;

    // Prologue: tile 0 -> buffer 0
    ra0 = *reinterpret_cast<const float4*>(Arow0);
    ra1 = *reinterpret_cast<const float4*>(Arow1);
    rb0 = *reinterpret_cast<const float4*>(Brow0);
    rb1 = *reinterpret_cast<const float4*>(Brow1);
    As[0][c0*4+0][r0] = ra0.x; As[0][c0*4+1][r0] = ra0.y;
    As[0][c0*4+2][r0] = ra0.z; As[0][c0*4+3][r0] = ra0.w;
    As[0][c1*4+0][r1] = ra1.x; As[0][c1*4+1][r1] = ra1.y;
    As[0][c1*4+2][r1] = ra1.z; As[0][c1*4+3][r1] = ra1.w;
    Bs[0][c0*4+0][r0] = rb0.x; Bs[0][c0*4+1][r0] = rb0.y;
    Bs[0][c0*4+2][r0] = rb0.z; Bs[0][c0*4+3][r0] = rb0.w;
    Bs[0][c1*4+0][r1] = rb1.x; Bs[0][c1*4+1][r1] = rb1.y;
    Bs[0][c1*4+2][r1] = rb1.z; Bs[0][c1*4+3][r1] = rb1.w;
    __syncthreads();

    for (int kt = 0; kt < G1_NT; kt++) {
        const int buf = kt & 1;

        if (kt + 1 < G1_NT) {
            const int koff = (kt + 1) * G1_BK;
            ra0 = *reinterpret_cast<const float4*>(Arow0 + koff);
            ra1 = *reinterpret_cast<const float4*>(Arow1 + koff);
            rb0 = *reinterpret_cast<const float4*>(Brow0 + koff);
            rb1 = *reinterpret_cast<const float4*>(Brow1 + koff);
        }

        #pragma unroll
        for (int k = 0; k < G1_BK; k++) {
            float a[G1_TM], b[G1_TN];
            #pragma unroll
            for (int i = 0; i < G1_TM; i += 4) {
                float4 v = *reinterpret_cast<const float4*>(&As[buf][k][ty * G1_TM + i]);
                a[i] = v.x; a[i+1] = v.y; a[i+2] = v.z; a[i+3] = v.w;
            }
            #pragma unroll
            for (int j = 0; j < G1_TN; j += 4) {
                float4 v = *reinterpret_cast<const float4*>(&Bs[buf][k][tx * G1_TN + j]);
                b[j] = v.x; b[j+1] = v.y; b[j+2] = v.z; b[j+3] = v.w;
            }
            #pragma unroll
            for (int i = 0; i < G1_TM; i++)
                #pragma unroll
                for (int j = 0; j < G1_TN; j++)
                    acc[i][j] = fmaf(a[i], b[j], acc[i][j]);
        }

        if (kt + 1 < G1_NT) {
            const int nb = 1 - buf;
            As[nb][c0*4+0][r0] = ra0.x; As[nb][c0*4+1][r0] = ra0.y;
            As[nb][c0*4+2][r0] = ra0.z; As[nb][c0*4+3][r0] = ra0.w;
            As[nb][c1*4+0][r1] = ra1.x; As[nb][c1*4+1][r1] = ra1.y;
            As[nb][c1*4+2][r1] = ra1.z; As[nb][c1*4+3][r1] = ra1.w;
            Bs[nb][c0*4+0][r0] = rb0.x; Bs[nb][c0*4+1][r0] = rb0.y;
            Bs[nb][c0*4+2][r0] = rb0.z; Bs[nb][c0*4+3][r0] = rb0.w;
            Bs[nb][c1*4+0][r1] = rb1.x; Bs[nb][c1*4+1][r1] = rb1.y;
            Bs[nb][c1*4+2][r1] = rb1.z; Bs[nb][c1*4+3][r1] = rb1.w;
        }
        __syncthreads();
    }

    #pragma unroll
    for (int i = 0; i < G1_TM; i++) {
        #pragma unroll
        for (int j = 0; j < G1_TN; j += 4) {
            float* cp = C + (size_t)(m0 + ty * G1_TM + i) * H_SZ + n0 + tx * G1_TN + j;
            if (ACCUM) {
                float4 prev = *reinterpret_cast<const float4*>(cp);
                float4 v = make_float4(__fadd_rn(prev.x, acc[i][j]),
                                       __fadd_rn(prev.y, acc[i][j+1]),
                                       __fadd_rn(prev.z, acc[i][j+2]),
                                       __fadd_rn(prev.w, acc[i][j+3]));
                *reinterpret_cast<float4*>(cp) = v;
            } else {
                float4 v = make_float4(acc[i][j], acc[i][j+1], acc[i][j+2], acc[i][j+3]);
                *reinterpret_cast<float4*>(cp) = v;
            }
        }
    }
}

// ---------------------------------------------------------------------------
// Fused timestep kernel: LIF1 + ordered compaction (smem) + sparse GEMM2 +
// LIF2. One CTA (256 threads) per batch row b. All accumulation orders
// identical to R8/R9 (bitwise contract): LIF single-rounding form; sparse
// ascending-k sum over W2T rows == dense serial ascending FMA chain.
// ---------------------------------------------------------------------------
__global__ __launch_bounds__(256)
void step_kernel(int t, float* __restrict__ out_ch, float* __restrict__ out_com)
{
    __shared__ int sk[H_SZ];    // spike k-indices, ascending (8 KB)
    __shared__ int sc[256];     // scan workspace

    const int b   = blockIdx.x;
    const int tid = threadIdx.x;
    const int PER = H_SZ / 256;   // 8

    // ---- LIF1 over this thread's contiguous k-chunk [tid*8, tid*8+8) ----
    const size_t hbase = ((size_t)b * T_STEPS + t) * H_SZ + (size_t)tid * PER;
    const size_t vbase = (size_t)b * H_SZ + (size_t)tid * PER;

    float h[PER], v[PER];
    #pragma unroll
    for (int j = 0; j < PER; j += 4) {
        float4 hv = *reinterpret_cast<const float4*>(&g_H[hbase + j]);
        h[j] = hv.x; h[j+1] = hv.y; h[j+2] = hv.z; h[j+3] = hv.w;
        float4 vv = *reinterpret_cast<const float4*>(&g_v1[vbase + j]);
        v[j] = vv.x; v[j+1] = vv.y; v[j+2] = vv.z; v[j+3] = vv.w;
    }

    float s[PER];
    int cnt = 0;
    #pragma unroll
    for (int j = 0; j < PER; j++) {
        float nv = __fmul_rn(__fadd_rn(v[j], h[j]), 0.5f);   // single rounding
        s[j] = (nv >= 0.5f) ? 1.0f : 0.0f;
        v[j] = (s[j] != 0.0f) ? 0.0f : nv;
        cnt += (s[j] != 0.0f) ? 1 : 0;
    }

    #pragma unroll
    for (int j = 0; j < PER; j += 4) {
        *reinterpret_cast<float4*>(&out_ch[hbase + j]) =
            make_float4(s[j], s[j+1], s[j+2], s[j+3]);
        *reinterpret_cast<float4*>(&g_v1[vbase + j]) =
            make_float4(v[j], v[j+1], v[j+2], v[j+3]);
    }

    // ---- block inclusive scan of spike counts (Hillis-Steele) ----
    sc[tid] = cnt;
    __syncthreads();
    #pragma unroll
    for (int off = 1; off < 256; off <<= 1) {
        int add = (tid >= off) ? sc[tid - off] : 0;
        __syncthreads();
        sc[tid] += add;
        __syncthreads();
    }
    int pos = sc[tid] - cnt;   // exclusive prefix

    #pragma unroll
    for (int j = 0; j < PER; j++)
        if (s[j] != 0.0f)
            sk[pos++] = tid * PER + j;

    const int total = sc[255];
    __syncthreads();   // sk fully written before reads

    // ---- sparse GEMM2: O[b, o] = sum over active k (ascending) W2T[k, o] ----
    const int o = tid * 4;
    float a0 = 0.0f, a1 = 0.0f, a2 = 0.0f, a3 = 0.0f;

    #pragma unroll 4
    for (int i = 0; i < total; i++) {
        const int k = sk[i];
        float4 w = *reinterpret_cast<const float4*>(&g_W2T[(size_t)k * OUT_SZ + o]);
        a0 = __fadd_rn(a0, w.x);
        a1 = __fadd_rn(a1, w.y);
        a2 = __fadd_rn(a2, w.z);
        a3 = __fadd_rn(a3, w.w);
    }

    // ---- LIF2 epilogue ----
    const size_t v2base = (size_t)b * OUT_SZ + o;
    float4 vv = *reinterpret_cast<const float4*>(&g_v2[v2base]);
    float acc[4] = {a0, a1, a2, a3};
    float vin[4] = {vv.x, vv.y, vv.z, vv.w};
    float sp[4], vout[4];
    #pragma unroll
    for (int j = 0; j < 4; j++) {
        float nv = __fmul_rn(__fadd_rn(vin[j], acc[j]), 0.5f);
        sp[j]   = (nv >= 0.5f) ? 1.0f : 0.0f;
        vout[j] = (sp[j] != 0.0f) ? 0.0f : nv;
    }
    *reinterpret_cast<float4*>(
        &out_com[((size_t)b * T_STEPS + t) * OUT_SZ + o]) =
        make_float4(sp[0], sp[1], sp[2], sp[3]);
    *reinterpret_cast<float4*>(&g_v2[v2base]) =
        make_float4(vout[0], vout[1], vout[2], vout[3]);
}

// ---------------------------------------------------------------------------
// kernel_launch: graph-capturable, allocation-free.
// Inputs: d_in[0]=x [B,T,F_IN] f32, d_in[1]=W1 [H,F_IN] f32, d_in[2]=W2 [OUT,H] f32
// Output: concat(com_spk [B,T,OUT], ch_spk [B,T,H], x [B,T,F_IN]) f32
// ---------------------------------------------------------------------------
extern "C" void kernel_launch(void* const* d_in, const int* in_sizes, int n_in,
                              void* d_out, int out_size)
{
    const float* x  = (const float*)d_in[0];
    const float* W1 = (const float*)d_in[1];
    const float* W2 = (const float*)d_in[2];
    float* out = (float*)d_out;

    const size_t COM_OFF = 0;
    const size_t CH_OFF  = (size_t)BT * OUT_SZ;
    const size_t X_OFF   = CH_OFF + (size_t)BT * H_SZ;

    float* out_com = out + COM_OFF;
    float* out_ch  = out + CH_OFF;
    float* out_x   = out + X_OFF;

    // 0) zero membranes + transpose W2
    {
        size_t n = (size_t)B_SZ * H_SZ;
        init_state_kernel<<<(unsigned)((n + 255) / 256), 256>>>();
        dim3 tgrid(H_SZ / 32, OUT_SZ / 32);
        transpose_w2_kernel<<<tgrid, dim3(32, 8)>>>(W2);
    }

    // 1) H = x @ W1^T — two kc=1024 phases (frozen accumulation order)
    {
        float* g_H_p;
        cudaGetSymbolAddress((void**)&g_H_p, g_H);
        dim3 grid(H_SZ / G1_BN, BT / G1_BM);   // (16, 64)
        gemm1_phase_kernel<false><<<grid, 256>>>(x, W1, g_H_p, 0);
        gemm1_phase_kernel<true ><<<grid, 256>>>(x, W1, g_H_p, G1_KC);
    }

    // 2) sequential timesteps: one fused kernel per step
    for (int t = 0; t < T_STEPS; t++)
        step_kernel<<<B_SZ, 256>>>(t, out_ch, out_com);

    // 3) passthrough x
    cudaMemcpyAsync(out_x, x, (size_t)BT * F_IN * sizeof(float),
                    cudaMemcpyDeviceToDevice, 0);

    (void)in_sizes; (void)n_in; (void)out_size;
}

// round 12
// speedup vs baseline: 2.1470x; 1.1202x over previous
#include <cuda_runtime.h>
#include <cstddef>

// Problem constants (fixed shapes from reference setup_inputs)
#define T_STEPS 16
#define B_SZ    512
#define F_IN    2048
#define H_SZ    2048
#define OUT_SZ  1024
#define BT      (B_SZ * T_STEPS)   // 8192

// Scratch (device globals: allocation-free per harness rules)
__device__ float g_H  [ (size_t)BT  * H_SZ   ];   // 64 MB: fc1 pre-activations, all t
__device__ float g_v1 [ (size_t)B_SZ * H_SZ  ];   // membrane lif1
__device__ float g_v2 [ (size_t)B_SZ * OUT_SZ];   // membrane lif_out
__device__ float g_W2T[ (size_t)H_SZ * OUT_SZ];   // 8 MB: W2 transposed [H, OUT]

// ---------------------------------------------------------------------------
// init: zero membranes
// ---------------------------------------------------------------------------
__global__ void init_state_kernel() {
    size_t i = (size_t)blockIdx.x * blockDim.x + threadIdx.x;
    size_t n1 = (size_t)B_SZ * H_SZ;
    size_t n2 = (size_t)B_SZ * OUT_SZ;
    if (i < n1) g_v1[i] = 0.0f;
    if (i < n2) g_v2[i] = 0.0f;
}

// ---------------------------------------------------------------------------
// Transpose W2 [OUT, H] -> W2T [H, OUT].  32x32 smem tiles.
// ---------------------------------------------------------------------------
__global__ void transpose_w2_kernel(const float* __restrict__ W2)
{
    __shared__ float tile[32][33];
    int o0 = blockIdx.y * 32;
    int k0 = blockIdx.x * 32;
    int tx = threadIdx.x, ty = threadIdx.y;   // 32 x 8

    #pragma unroll
    for (int r = 0; r < 32; r += 8)
        tile[ty + r][tx] = W2[(size_t)(o0 + ty + r) * H_SZ + k0 + tx];
    __syncthreads();
    #pragma unroll
    for (int r = 0; r < 32; r += 8)
        g_W2T[(size_t)(k0 + ty + r) * OUT_SZ + o0 + tx] = tile[tx][ty + r];
}

// ---------------------------------------------------------------------------
// GEMM1 phase kernel (H = x @ W1^T, one kc=1024 chunk per launch).
// ACCUMULATION CONTRACT (frozen, R6): per element, 2 contiguous chunks of
// 1024, each a serial ascending FMA chain from zero, merged sequentially.
//   Phase A (ACCUM=false): C  = chain(K[0:1024])
//   Phase B (ACCUM=true):  C  = __fadd_rn(C, chain(K[1024:2048]))
// R11/R12: __launch_bounds__(256, 2) caps regs at 128 -> 2 CTAs/SM -> 4
// warps per scheduler for latency hiding (R10 measured 130 regs, occ=12.5%,
// fma=44% — latency-bound at 1 CTA/SM).
// BM=BN=128, BK=16, TM=TN=8, 256 threads. Grid (16, 64).
// ---------------------------------------------------------------------------
#define G1_BM 128
#define G1_BN 128
#define G1_BK 16
#define G1_TM 8
#define G1_TN 8
#define G1_KC 1024
#define G1_NT (G1_KC / G1_BK)   // 64 tiles per phase

template<bool ACCUM>
__global__ __launch_bounds__(256, 2)
void gemm1_phase_kernel(const float* __restrict__ A,    // x   [BT, F_IN]
                        const float* __restrict__ Bm,   // W1  [H, F_IN]
                        float* __restrict__ C,          // g_H [BT, H]
                        int k_base)
{
    __shared__ float As[2][G1_BK][G1_BM];
    __shared__ float Bs[2][G1_BK][G1_BN];

    const int tid = threadIdx.x;
    const int m0  = blockIdx.y * G1_BM;
    const int n0  = blockIdx.x * G1_BN;
    const int ty  = tid / (G1_BN / G1_TN);
    const int tx  = tid % (G1_BN / G1_TN);

    const int r0 = tid >> 2;
    const int c0 = tid & 3;
    const int r1 = (tid + 256) >> 2;
    const int c1 = (tid + 256) & 3;

    const float* Arow0 = A  + (size_t)(m0 + r0) * F_IN + k_base + c0 * 4;
    const float* Arow1 = A  + (size_t)(m0 + r1) * F_IN + k_base + c1 * 4;
    const float* Brow0 = Bm + (size_t)(n0 + r0) * F_IN + k_base + c0 * 4;
    const float* Brow1 = Bm + (size_t)(n0 + r1) * F_IN + k_base + c1 * 4;

    float acc[G1_TM][G1_TN];
    #pragma unroll
    for (int i = 0; i < G1_TM; i++)
        #pragma unroll
        for (int j = 0; j < G1_TN; j++)
            acc[i][j] = 0.0f;

    float4 ra0, ra1, rb0, rb1;

    // Prologue: tile 0 -> buffer 0
    ra0 = *reinterpret_cast<const float4*>(Arow0);
    ra1 = *reinterpret_cast<const float4*>(Arow1);
    rb0 = *reinterpret_cast<const float4*>(Brow0);
    rb1 = *reinterpret_cast<const float4*>(Brow1);
    As[0][c0*4+0][r0] = ra0.x; As[0][c0*4+1][r0] = ra0.y;
    As[0][c0*4+2][r0] = ra0.z; As[0][c0*4+3][r0] = ra0.w;
    As[0][c1*4+0][r1] = ra1.x; As[0][c1*4+1][r1] = ra1.y;
    As[0][c1*4+2][r1] = ra1.z; As[0][c1*4+3][r1] = ra1.w;
    Bs[0][c0*4+0][r0] = rb0.x; Bs[0][c0*4+1][r0] = rb0.y;
    Bs[0][c0*4+2][r0] = rb0.z; Bs[0][c0*4+3][r0] = rb0.w;
    Bs[0][c1*4+0][r1] = rb1.x; Bs[0][c1*4+1][r1] = rb1.y;
    Bs[0][c1*4+2][r1] = rb1.z; Bs[0][c1*4+3][r1] = rb1.w;
    __syncthreads();

    for (int kt = 0; kt < G1_NT; kt++) {
        const int buf = kt & 1;

        if (kt + 1 < G1_NT) {
            const int koff = (kt + 1) * G1_BK;
            ra0 = *reinterpret_cast<const float4*>(Arow0 + koff);
            ra1 = *reinterpret_cast<const float4*>(Arow1 + koff);
            rb0 = *reinterpret_cast<const float4*>(Brow0 + koff);
            rb1 = *reinterpret_cast<const float4*>(Brow1 + koff);
        }

        #pragma unroll
        for (int k = 0; k < G1_BK; k++) {
            float a[G1_TM], b[G1_TN];
            #pragma unroll
            for (int i = 0; i < G1_TM; i += 4) {
                float4 v = *reinterpret_cast<const float4*>(&As[buf][k][ty * G1_TM + i]);
                a[i] = v.x; a[i+1] = v.y; a[i+2] = v.z; a[i+3] = v.w;
            }
            #pragma unroll
            for (int j = 0; j < G1_TN; j += 4) {
                float4 v = *reinterpret_cast<const float4*>(&Bs[buf][k][tx * G1_TN + j]);
                b[j] = v.x; b[j+1] = v.y; b[j+2] = v.z; b[j+3] = v.w;
            }
            #pragma unroll
            for (int i = 0; i < G1_TM; i++)
                #pragma unroll
                for (int j = 0; j < G1_TN; j++)
                    acc[i][j] = fmaf(a[i], b[j], acc[i][j]);
        }

        if (kt + 1 < G1_NT) {
            const int nb = 1 - buf;
            As[nb][c0*4+0][r0] = ra0.x; As[nb][c0*4+1][r0] = ra0.y;
            As[nb][c0*4+2][r0] = ra0.z; As[nb][c0*4+3][r0] = ra0.w;
            As[nb][c1*4+0][r1] = ra1.x; As[nb][c1*4+1][r1] = ra1.y;
            As[nb][c1*4+2][r1] = ra1.z; As[nb][c1*4+3][r1] = ra1.w;
            Bs[nb][c0*4+0][r0] = rb0.x; Bs[nb][c0*4+1][r0] = rb0.y;
            Bs[nb][c0*4+2][r0] = rb0.z; Bs[nb][c0*4+3][r0] = rb0.w;
            Bs[nb][c1*4+0][r1] = rb1.x; Bs[nb][c1*4+1][r1] = rb1.y;
            Bs[nb][c1*4+2][r1] = rb1.z; Bs[nb][c1*4+3][r1] = rb1.w;
        }
        __syncthreads();
    }

    #pragma unroll
    for (int i = 0; i < G1_TM; i++) {
        #pragma unroll
        for (int j = 0; j < G1_TN; j += 4) {
            float* cp = C + (size_t)(m0 + ty * G1_TM + i) * H_SZ + n0 + tx * G1_TN + j;
            if (ACCUM) {
                float4 prev = *reinterpret_cast<const float4*>(cp);
                float4 v = make_float4(__fadd_rn(prev.x, acc[i][j]),
                                       __fadd_rn(prev.y, acc[i][j+1]),
                                       __fadd_rn(prev.z, acc[i][j+2]),
                                       __fadd_rn(prev.w, acc[i][j+3]));
                *reinterpret_cast<float4*>(cp) = v;
            } else {
                float4 v = make_float4(acc[i][j], acc[i][j+1], acc[i][j+2], acc[i][j+3]);
                *reinterpret_cast<float4*>(cp) = v;
            }
        }
    }
}

// ---------------------------------------------------------------------------
// Fused timestep kernel: LIF1 + ordered compaction (smem) + sparse GEMM2 +
// LIF2. One CTA (256 threads) per batch row b. All accumulation orders
// identical to R8-R10 (bitwise contract): LIF single-rounding form; sparse
// ascending-k sum over W2T rows == dense serial ascending FMA chain.
// ---------------------------------------------------------------------------
__global__ __launch_bounds__(256)
void step_kernel(int t, float* __restrict__ out_ch, float* __restrict__ out_com)
{
    __shared__ int sk[H_SZ];    // spike k-indices, ascending (8 KB)
    __shared__ int sc[256];     // scan workspace

    const int b   = blockIdx.x;
    const int tid = threadIdx.x;
    const int PER = H_SZ / 256;   // 8

    // ---- LIF1 over this thread's contiguous k-chunk [tid*8, tid*8+8) ----
    const size_t hbase = ((size_t)b * T_STEPS + t) * H_SZ + (size_t)tid * PER;
    const size_t vbase = (size_t)b * H_SZ + (size_t)tid * PER;

    float h[PER], v[PER];
    #pragma unroll
    for (int j = 0; j < PER; j += 4) {
        float4 hv = *reinterpret_cast<const float4*>(&g_H[hbase + j]);
        h[j] = hv.x; h[j+1] = hv.y; h[j+2] = hv.z; h[j+3] = hv.w;
        float4 vv = *reinterpret_cast<const float4*>(&g_v1[vbase + j]);
        v[j] = vv.x; v[j+1] = vv.y; v[j+2] = vv.z; v[j+3] = vv.w;
    }

    float s[PER];
    int cnt = 0;
    #pragma unroll
    for (int j = 0; j < PER; j++) {
        float nv = __fmul_rn(__fadd_rn(v[j], h[j]), 0.5f);   // single rounding
        s[j] = (nv >= 0.5f) ? 1.0f : 0.0f;
        v[j] = (s[j] != 0.0f) ? 0.0f : nv;
        cnt += (s[j] != 0.0f) ? 1 : 0;
    }

    #pragma unroll
    for (int j = 0; j < PER; j += 4) {
        *reinterpret_cast<float4*>(&out_ch[hbase + j]) =
            make_float4(s[j], s[j+1], s[j+2], s[j+3]);
        *reinterpret_cast<float4*>(&g_v1[vbase + j]) =
            make_float4(v[j], v[j+1], v[j+2], v[j+3]);
    }

    // ---- block inclusive scan of spike counts (Hillis-Steele) ----
    sc[tid] = cnt;
    __syncthreads();
    #pragma unroll
    for (int off = 1; off < 256; off <<= 1) {
        int add = (tid >= off) ? sc[tid - off] : 0;
        __syncthreads();
        sc[tid] += add;
        __syncthreads();
    }
    int pos = sc[tid] - cnt;   // exclusive prefix

    #pragma unroll
    for (int j = 0; j < PER; j++)
        if (s[j] != 0.0f)
            sk[pos++] = tid * PER + j;

    const int total = sc[255];
    __syncthreads();   // sk fully written before reads

    // ---- sparse GEMM2: O[b, o] = sum over active k (ascending) W2T[k, o] ----
    const int o = tid * 4;
    float a0 = 0.0f, a1 = 0.0f, a2 = 0.0f, a3 = 0.0f;

    #pragma unroll 4
    for (int i = 0; i < total; i++) {
        const int k = sk[i];
        float4 w = *reinterpret_cast<const float4*>(&g_W2T[(size_t)k * OUT_SZ + o]);
        a0 = __fadd_rn(a0, w.x);
        a1 = __fadd_rn(a1, w.y);
        a2 = __fadd_rn(a2, w.z);
        a3 = __fadd_rn(a3, w.w);
    }

    // ---- LIF2 epilogue ----
    const size_t v2base = (size_t)b * OUT_SZ + o;
    float4 vv = *reinterpret_cast<const float4*>(&g_v2[v2base]);
    float acc[4] = {a0, a1, a2, a3};
    float vin[4] = {vv.x, vv.y, vv.z, vv.w};
    float sp[4], vout[4];
    #pragma unroll
    for (int j = 0; j < 4; j++) {
        float nv = __fmul_rn(__fadd_rn(vin[j], acc[j]), 0.5f);
        sp[j]   = (nv >= 0.5f) ? 1.0f : 0.0f;
        vout[j] = (sp[j] != 0.0f) ? 0.0f : nv;
    }
    *reinterpret_cast<float4*>(
        &out_com[((size_t)b * T_STEPS + t) * OUT_SZ + o]) =
        make_float4(sp[0], sp[1], sp[2], sp[3]);
    *reinterpret_cast<float4*>(&g_v2[v2base]) =
        make_float4(vout[0], vout[1], vout[2], vout[3]);
}

// ---------------------------------------------------------------------------
// kernel_launch: graph-capturable, allocation-free.
// Inputs: d_in[0]=x [B,T,F_IN] f32, d_in[1]=W1 [H,F_IN] f32, d_in[2]=W2 [OUT,H] f32
// Output: concat(com_spk [B,T,OUT], ch_spk [B,T,H], x [B,T,F_IN]) f32
// ---------------------------------------------------------------------------
extern "C" void kernel_launch(void* const* d_in, const int* in_sizes, int n_in,
                              void* d_out, int out_size)
{
    const float* x  = (const float*)d_in[0];
    const float* W1 = (const float*)d_in[1];
    const float* W2 = (const float*)d_in[2];
    float* out = (float*)d_out;

    const size_t COM_OFF = 0;
    const size_t CH_OFF  = (size_t)BT * OUT_SZ;
    const size_t X_OFF   = CH_OFF + (size_t)BT * H_SZ;

    float* out_com = out + COM_OFF;
    float* out_ch  = out + CH_OFF;
    float* out_x   = out + X_OFF;

    // 0) zero membranes + transpose W2
    {
        size_t n = (size_t)B_SZ * H_SZ;
        init_state_kernel<<<(unsigned)((n + 255) / 256), 256>>>();
        dim3 tgrid(H_SZ / 32, OUT_SZ / 32);
        transpose_w2_kernel<<<tgrid, dim3(32, 8)>>>(W2);
    }

    // 1) H = x @ W1^T — two kc=1024 phases (frozen accumulation order)
    {
        float* g_H_p;
        cudaGetSymbolAddress((void**)&g_H_p, g_H);
        dim3 grid(H_SZ / G1_BN, BT / G1_BM);   // (16, 64)
        gemm1_phase_kernel<false><<<grid, 256>>>(x, W1, g_H_p, 0);
        gemm1_phase_kernel<true ><<<grid, 256>>>(x, W1, g_H_p, G1_KC);
    }

    // 2) sequential timesteps: one fused kernel per step
    for (int t = 0; t < T_STEPS; t++)
        step_kernel<<<B_SZ, 256>>>(t, out_ch, out_com);

    // 3) passthrough x
    cudaMemcpyAsync(out_x, x, (size_t)BT * F_IN * sizeof(float),
                    cudaMemcpyDeviceToDevice, 0);

    (void)in_sizes; (void)n_in; (void)out_size;
}

// round 13
// speedup vs baseline: 2.3345x; 1.0873x over previous
#include <cuda_runtime.h>
#include <cstddef>

// Problem constants (fixed shapes from reference setup_inputs)
#define T_STEPS 16
#define B_SZ    512
#define F_IN    2048
#define H_SZ    2048
#define OUT_SZ  1024
#define BT      (B_SZ * T_STEPS)   // 8192

// Scratch (device globals: allocation-free per harness rules)
__device__ float g_H  [ (size_t)BT  * H_SZ   ];   // 64 MB: fc1 pre-activations, all t
__device__ float g_v1 [ (size_t)B_SZ * H_SZ  ];   // membrane lif1
__device__ float g_v2 [ (size_t)B_SZ * OUT_SZ];   // membrane lif_out
__device__ float g_W2T[ (size_t)H_SZ * OUT_SZ];   // 8 MB: W2 transposed [H, OUT]

// ---------------------------------------------------------------------------
// init: zero membranes
// ---------------------------------------------------------------------------
__global__ void init_state_kernel() {
    size_t i = (size_t)blockIdx.x * blockDim.x + threadIdx.x;
    size_t n1 = (size_t)B_SZ * H_SZ;
    size_t n2 = (size_t)B_SZ * OUT_SZ;
    if (i < n1) g_v1[i] = 0.0f;
    if (i < n2) g_v2[i] = 0.0f;
}

// ---------------------------------------------------------------------------
// Transpose W2 [OUT, H] -> W2T [H, OUT].  32x32 smem tiles.
// ---------------------------------------------------------------------------
__global__ void transpose_w2_kernel(const float* __restrict__ W2)
{
    __shared__ float tile[32][33];
    int o0 = blockIdx.y * 32;
    int k0 = blockIdx.x * 32;
    int tx = threadIdx.x, ty = threadIdx.y;   // 32 x 8

    #pragma unroll
    for (int r = 0; r < 32; r += 8)
        tile[ty + r][tx] = W2[(size_t)(o0 + ty + r) * H_SZ + k0 + tx];
    __syncthreads();
    #pragma unroll
    for (int r = 0; r < 32; r += 8)
        g_W2T[(size_t)(k0 + ty + r) * OUT_SZ + o0 + tx] = tile[tx][ty + r];
}

// ---------------------------------------------------------------------------
// GEMM1 phase kernel (H = x @ W1^T, one kc=1024 chunk per launch).
// ACCUMULATION CONTRACT (frozen, R6): per element, 2 contiguous chunks of
// 1024, each a serial ascending FMA chain from zero, merged sequentially.
//   Phase A (ACCUM=false): C  = chain(K[0:1024])
//   Phase B (ACCUM=true):  C  = __fadd_rn(C, chain(K[1024:2048]))
// R13: strided-fragment thread mapping to kill smem wavefronts (R12 ncu:
// L1=94.8%, fma=57.7% — crossbar-bound). Warp = 8x4 lanes; each thread owns
// rows {r..r+3, r+64..r+67} x cols {c..c+3, c+64..c+67}. As LDS.128 = 8
// contiguous 16B lines = 1 wavefront; Bs LDS.128 = 64B broadcast.
// Ownership remap only — every element keeps the identical serial chain.
// BM=BN=128, BK=16, 256 threads, 2 CTAs/SM. Grid (16, 64).
// ---------------------------------------------------------------------------
#define G1_BM 128
#define G1_BN 128
#define G1_BK 16
#define G1_KC 1024
#define G1_NT (G1_KC / G1_BK)   // 64 tiles per phase

template<bool ACCUM>
__global__ __launch_bounds__(256, 2)
void gemm1_phase_kernel(const float* __restrict__ A,    // x   [BT, F_IN]
                        const float* __restrict__ Bm,   // W1  [H, F_IN]
                        float* __restrict__ C,          // g_H [BT, H]
                        int k_base)
{
    __shared__ float As[2][G1_BK][G1_BM];
    __shared__ float Bs[2][G1_BK][G1_BN];

    const int tid  = threadIdx.x;
    const int m0   = blockIdx.y * G1_BM;
    const int n0   = blockIdx.x * G1_BN;

    // Strided-fragment mapping: warp 8x4, CTA warps 2x4.
    const int lane = tid & 31;
    const int warp = tid >> 5;
    const int ly   = lane >> 2;          // 0..7
    const int lx   = lane & 3;           // 0..3
    const int wy   = warp >> 2;          // 0..1
    const int wx   = warp & 3;           // 0..3
    const int rr   = (wy * 8 + ly) * 4;  // row base 0..124 (step 4)
    const int cc   = (wx * 4 + lx) * 4;  // col base 0..60  (step 4)

    // Staging (global->smem) mapping unchanged from R12.
    const int r0 = tid >> 2;
    const int c0 = tid & 3;
    const int r1 = (tid + 256) >> 2;
    const int c1 = (tid + 256) & 3;

    const float* Arow0 = A  + (size_t)(m0 + r0) * F_IN + k_base + c0 * 4;
    const float* Arow1 = A  + (size_t)(m0 + r1) * F_IN + k_base + c1 * 4;
    const float* Brow0 = Bm + (size_t)(n0 + r0) * F_IN + k_base + c0 * 4;
    const float* Brow1 = Bm + (size_t)(n0 + r1) * F_IN + k_base + c1 * 4;

    float acc[8][8];
    #pragma unroll
    for (int i = 0; i < 8; i++)
        #pragma unroll
        for (int j = 0; j < 8; j++)
            acc[i][j] = 0.0f;

    float4 ra0, ra1, rb0, rb1;

    // Prologue: tile 0 -> buffer 0
    ra0 = *reinterpret_cast<const float4*>(Arow0);
    ra1 = *reinterpret_cast<const float4*>(Arow1);
    rb0 = *reinterpret_cast<const float4*>(Brow0);
    rb1 = *reinterpret_cast<const float4*>(Brow1);
    As[0][c0*4+0][r0] = ra0.x; As[0][c0*4+1][r0] = ra0.y;
    As[0][c0*4+2][r0] = ra0.z; As[0][c0*4+3][r0] = ra0.w;
    As[0][c1*4+0][r1] = ra1.x; As[0][c1*4+1][r1] = ra1.y;
    As[0][c1*4+2][r1] = ra1.z; As[0][c1*4+3][r1] = ra1.w;
    Bs[0][c0*4+0][r0] = rb0.x; Bs[0][c0*4+1][r0] = rb0.y;
    Bs[0][c0*4+2][r0] = rb0.z; Bs[0][c0*4+3][r0] = rb0.w;
    Bs[0][c1*4+0][r1] = rb1.x; Bs[0][c1*4+1][r1] = rb1.y;
    Bs[0][c1*4+2][r1] = rb1.z; Bs[0][c1*4+3][r1] = rb1.w;
    __syncthreads();

    for (int kt = 0; kt < G1_NT; kt++) {
        const int buf = kt & 1;

        if (kt + 1 < G1_NT) {
            const int koff = (kt + 1) * G1_BK;
            ra0 = *reinterpret_cast<const float4*>(Arow0 + koff);
            ra1 = *reinterpret_cast<const float4*>(Arow1 + koff);
            rb0 = *reinterpret_cast<const float4*>(Brow0 + koff);
            rb1 = *reinterpret_cast<const float4*>(Brow1 + koff);
        }

        #pragma unroll
        for (int k = 0; k < G1_BK; k++) {
            float4 a_lo = *reinterpret_cast<const float4*>(&As[buf][k][rr]);
            float4 a_hi = *reinterpret_cast<const float4*>(&As[buf][k][rr + 64]);
            float4 b_lo = *reinterpret_cast<const float4*>(&Bs[buf][k][cc]);
            float4 b_hi = *reinterpret_cast<const float4*>(&Bs[buf][k][cc + 64]);
            float a[8] = {a_lo.x, a_lo.y, a_lo.z, a_lo.w,
                          a_hi.x, a_hi.y, a_hi.z, a_hi.w};
            float b[8] = {b_lo.x, b_lo.y, b_lo.z, b_lo.w,
                          b_hi.x, b_hi.y, b_hi.z, b_hi.w};
            #pragma unroll
            for (int i = 0; i < 8; i++)
                #pragma unroll
                for (int j = 0; j < 8; j++)
                    acc[i][j] = fmaf(a[i], b[j], acc[i][j]);
        }

        if (kt + 1 < G1_NT) {
            const int nb = 1 - buf;
            As[nb][c0*4+0][r0] = ra0.x; As[nb][c0*4+1][r0] = ra0.y;
            As[nb][c0*4+2][r0] = ra0.z; As[nb][c0*4+3][r0] = ra0.w;
            As[nb][c1*4+0][r1] = ra1.x; As[nb][c1*4+1][r1] = ra1.y;
            As[nb][c1*4+2][r1] = ra1.z; As[nb][c1*4+3][r1] = ra1.w;
            Bs[nb][c0*4+0][r0] = rb0.x; Bs[nb][c0*4+1][r0] = rb0.y;
            Bs[nb][c0*4+2][r0] = rb0.z; Bs[nb][c0*4+3][r0] = rb0.w;
            Bs[nb][c1*4+0][r1] = rb1.x; Bs[nb][c1*4+1][r1] = rb1.y;
            Bs[nb][c1*4+2][r1] = rb1.z; Bs[nb][c1*4+3][r1] = rb1.w;
        }
        __syncthreads();
    }

    // Epilogue: rows {rr+i, rr+64+i}, cols {cc..cc+3, cc+64..cc+67}
    #pragma unroll
    for (int i = 0; i < 8; i++) {
        const int row = m0 + ((i < 4) ? (rr + i) : (rr + 64 + i - 4));
        #pragma unroll
        for (int jh = 0; jh < 2; jh++) {
            const int col = n0 + cc + jh * 64;
            float* cp = C + (size_t)row * H_SZ + col;
            const int j0 = jh * 4;
            if (ACCUM) {
                float4 prev = *reinterpret_cast<const float4*>(cp);
                float4 v = make_float4(__fadd_rn(prev.x, acc[i][j0+0]),
                                       __fadd_rn(prev.y, acc[i][j0+1]),
                                       __fadd_rn(prev.z, acc[i][j0+2]),
                                       __fadd_rn(prev.w, acc[i][j0+3]));
                *reinterpret_cast<float4*>(cp) = v;
            } else {
                float4 v = make_float4(acc[i][j0+0], acc[i][j0+1],
                                       acc[i][j0+2], acc[i][j0+3]);
                *reinterpret_cast<float4*>(cp) = v;
            }
        }
    }
}

// ---------------------------------------------------------------------------
// Fused timestep kernel: LIF1 + ordered compaction (smem) + sparse GEMM2 +
// LIF2. One CTA (256 threads) per batch row b. All accumulation orders
// identical to R8-R12 (bitwise contract): LIF single-rounding form; sparse
// ascending-k sum over W2T rows == dense serial ascending FMA chain.
// ---------------------------------------------------------------------------
__global__ __launch_bounds__(256)
void step_kernel(int t, float* __restrict__ out_ch, float* __restrict__ out_com)
{
    __shared__ int sk[H_SZ];    // spike k-indices, ascending (8 KB)
    __shared__ int sc[256];     // scan workspace

    const int b   = blockIdx.x;
    const int tid = threadIdx.x;
    const int PER = H_SZ / 256;   // 8

    // ---- LIF1 over this thread's contiguous k-chunk [tid*8, tid*8+8) ----
    const size_t hbase = ((size_t)b * T_STEPS + t) * H_SZ + (size_t)tid * PER;
    const size_t vbase = (size_t)b * H_SZ + (size_t)tid * PER;

    float h[PER], v[PER];
    #pragma unroll
    for (int j = 0; j < PER; j += 4) {
        float4 hv = *reinterpret_cast<const float4*>(&g_H[hbase + j]);
        h[j] = hv.x; h[j+1] = hv.y; h[j+2] = hv.z; h[j+3] = hv.w;
        float4 vv = *reinterpret_cast<const float4*>(&g_v1[vbase + j]);
        v[j] = vv.x; v[j+1] = vv.y; v[j+2] = vv.z; v[j+3] = vv.w;
    }

    float s[PER];
    int cnt = 0;
    #pragma unroll
    for (int j = 0; j < PER; j++) {
        float nv = __fmul_rn(__fadd_rn(v[j], h[j]), 0.5f);   // single rounding
        s[j] = (nv >= 0.5f) ? 1.0f : 0.0f;
        v[j] = (s[j] != 0.0f) ? 0.0f : nv;
        cnt += (s[j] != 0.0f) ? 1 : 0;
    }

    #pragma unroll
    for (int j = 0; j < PER; j += 4) {
        *reinterpret_cast<float4*>(&out_ch[hbase + j]) =
            make_float4(s[j], s[j+1], s[j+2], s[j+3]);
        *reinterpret_cast<float4*>(&g_v1[vbase + j]) =
            make_float4(v[j], v[j+1], v[j+2], v[j+3]);
    }

    // ---- block inclusive scan of spike counts (Hillis-Steele) ----
    sc[tid] = cnt;
    __syncthreads();
    #pragma unroll
    for (int off = 1; off < 256; off <<= 1) {
        int add = (tid >= off) ? sc[tid - off] : 0;
        __syncthreads();
        sc[tid] += add;
        __syncthreads();
    }
    int pos = sc[tid] - cnt;   // exclusive prefix

    #pragma unroll
    for (int j = 0; j < PER; j++)
        if (s[j] != 0.0f)
            sk[pos++] = tid * PER + j;

    const int total = sc[255];
    __syncthreads();   // sk fully written before reads

    // ---- sparse GEMM2: O[b, o] = sum over active k (ascending) W2T[k, o] ----
    const int o = tid * 4;
    float a0 = 0.0f, a1 = 0.0f, a2 = 0.0f, a3 = 0.0f;

    #pragma unroll 4
    for (int i = 0; i < total; i++) {
        const int k = sk[i];
        float4 w = *reinterpret_cast<const float4*>(&g_W2T[(size_t)k * OUT_SZ + o]);
        a0 = __fadd_rn(a0, w.x);
        a1 = __fadd_rn(a1, w.y);
        a2 = __fadd_rn(a2, w.z);
        a3 = __fadd_rn(a3, w.w);
    }

    // ---- LIF2 epilogue ----
    const size_t v2base = (size_t)b * OUT_SZ + o;
    float4 vv = *reinterpret_cast<const float4*>(&g_v2[v2base]);
    float acc[4] = {a0, a1, a2, a3};
    float vin[4] = {vv.x, vv.y, vv.z, vv.w};
    float sp[4], vout[4];
    #pragma unroll
    for (int j = 0; j < 4; j++) {
        float nv = __fmul_rn(__fadd_rn(vin[j], acc[j]), 0.5f);
        sp[j]   = (nv >= 0.5f) ? 1.0f : 0.0f;
        vout[j] = (sp[j] != 0.0f) ? 0.0f : nv;
    }
    *reinterpret_cast<float4*>(
        &out_com[((size_t)b * T_STEPS + t) * OUT_SZ + o]) =
        make_float4(sp[0], sp[1], sp[2], sp[3]);
    *reinterpret_cast<float4*>(&g_v2[v2base]) =
        make_float4(vout[0], vout[1], vout[2], vout[3]);
}

// ---------------------------------------------------------------------------
// kernel_launch: graph-capturable, allocation-free.
// Inputs: d_in[0]=x [B,T,F_IN] f32, d_in[1]=W1 [H,F_IN] f32, d_in[2]=W2 [OUT,H] f32
// Output: concat(com_spk [B,T,OUT], ch_spk [B,T,H], x [B,T,F_IN]) f32
// ---------------------------------------------------------------------------
extern "C" void kernel_launch(void* const* d_in, const int* in_sizes, int n_in,
                              void* d_out, int out_size)
{
    const float* x  = (const float*)d_in[0];
    const float* W1 = (const float*)d_in[1];
    const float* W2 = (const float*)d_in[2];
    float* out = (float*)d_out;

    const size_t COM_OFF = 0;
    const size_t CH_OFF  = (size_t)BT * OUT_SZ;
    const size_t X_OFF   = CH_OFF + (size_t)BT * H_SZ;

    float* out_com = out + COM_OFF;
    float* out_ch  = out + CH_OFF;
    float* out_x   = out + X_OFF;

    // 0) zero membranes + transpose W2
    {
        size_t n = (size_t)B_SZ * H_SZ;
        init_state_kernel<<<(unsigned)((n + 255) / 256), 256>>>();
        dim3 tgrid(H_SZ / 32, OUT_SZ / 32);
        transpose_w2_kernel<<<tgrid, dim3(32, 8)>>>(W2);
    }

    // 1) H = x @ W1^T — two kc=1024 phases (frozen accumulation order)
    {
        float* g_H_p;
        cudaGetSymbolAddress((void**)&g_H_p, g_H);
        dim3 grid(H_SZ / G1_BN, BT / G1_BM);   // (16, 64)
        gemm1_phase_kernel<false><<<grid, 256>>>(x, W1, g_H_p, 0);
        gemm1_phase_kernel<true ><<<grid, 256>>>(x, W1, g_H_p, G1_KC);
    }

    // 2) sequential timesteps: one fused kernel per step
    for (int t = 0; t < T_STEPS; t++)
        step_kernel<<<B_SZ, 256>>>(t, out_ch, out_com);

    // 3) passthrough x
    cudaMemcpyAsync(out_x, x, (size_t)BT * F_IN * sizeof(float),
                    cudaMemcpyDeviceToDevice, 0);

    (void)in_sizes; (void)n_in; (void)out_size;
}